// round 6
// baseline (speedup 1.0000x reference)
#include <cuda_runtime.h>
#include <cuda_bf16.h>
#include <cstdint>
#include <math.h>

#define D_MODEL 1024
#define NHEADS  16
#define DEPTH   64
#define BATCH   2
#define SEQ     2048
#define NROWS   (BATCH * SEQ)   // 4096

// ---------------- scratch (no allocation allowed) ----------------
__device__ float g_q[NROWS * D_MODEL];
__device__ float g_k[NROWS * D_MODEL];
__device__ float g_v[NROWS * D_MODEL];
__device__ float g_o[NROWS * D_MODEL];
__device__ __nv_bfloat16 s_ahi[NROWS * D_MODEL];
__device__ __nv_bfloat16 s_alo[NROWS * D_MODEL];
__device__ __nv_bfloat16 s_whi[D_MODEL * D_MODEL];
__device__ __nv_bfloat16 s_wlo[D_MODEL * D_MODEL];

// ---------------- helpers ----------------
__device__ __forceinline__ uint32_t smem_u32(const void* p) {
    uint32_t a;
    asm("{ .reg .u64 t; cvta.to.shared.u64 t, %1; cvt.u32.u64 %0, t; }" : "=r"(a) : "l"(p));
    return a;
}
__device__ __forceinline__ void ldmatrix_x4(uint32_t* r, uint32_t addr) {
    asm volatile("ldmatrix.sync.aligned.m8n8.x4.shared.b16 {%0,%1,%2,%3}, [%4];"
                 : "=r"(r[0]), "=r"(r[1]), "=r"(r[2]), "=r"(r[3]) : "r"(addr));
}
__device__ __forceinline__ void ldmatrix_x2(uint32_t* r, uint32_t addr) {
    asm volatile("ldmatrix.sync.aligned.m8n8.x2.shared.b16 {%0,%1}, [%2];"
                 : "=r"(r[0]), "=r"(r[1]) : "r"(addr));
}
__device__ __forceinline__ void mma_bf16(float* c, const uint32_t* a, const uint32_t* b) {
    asm volatile(
        "mma.sync.aligned.m16n8k16.row.col.f32.bf16.bf16.f32 "
        "{%0,%1,%2,%3}, {%4,%5,%6,%7}, {%8,%9}, {%0,%1,%2,%3};"
        : "+f"(c[0]), "+f"(c[1]), "+f"(c[2]), "+f"(c[3])
        : "r"(a[0]), "r"(a[1]), "r"(a[2]), "r"(a[3]), "r"(b[0]), "r"(b[1]));
}
__device__ __forceinline__ void split_pack(float x, float y, uint32_t& hi, uint32_t& lo) {
    __nv_bfloat162 h = __floats2bfloat162_rn(x, y);
    float hx = __bfloat162float(__low2bfloat16(h));
    float hy = __bfloat162float(__high2bfloat16(h));
    __nv_bfloat162 l = __floats2bfloat162_rn(x - hx, y - hy);
    hi = *(uint32_t*)&h;
    lo = *(uint32_t*)&l;
}

// ---------------------------------------------------------------------------
// split fp32 -> (hi, lo) bf16 pair
// ---------------------------------------------------------------------------
__global__ __launch_bounds__(256) void split_bf16(
    const float* __restrict__ x, __nv_bfloat16* __restrict__ hi,
    __nv_bfloat16* __restrict__ lo, int n4)
{
    int i = blockIdx.x * blockDim.x + threadIdx.x;
    if (i >= n4) return;
    float4 v = ((const float4*)x)[i];
    uint32_t h0, l0, h1, l1;
    split_pack(v.x, v.y, h0, l0);
    split_pack(v.z, v.w, h1, l1);
    ((uint32_t*)hi)[2 * i]     = h0;
    ((uint32_t*)hi)[2 * i + 1] = h1;
    ((uint32_t*)lo)[2 * i]     = l0;
    ((uint32_t*)lo)[2 * i + 1] = l1;
}

// ---------------------------------------------------------------------------
// mma.sync split-bf16 GEMM-NT: C[M,N] = A[M,K] @ W[N,K]^T + bias  (validated)
// ---------------------------------------------------------------------------
#define GK 1024
#define GN 1024
#define BKC 32
#define LDSG 40

__global__ __launch_bounds__(256, 2) void gemm_mma_split(
    const __nv_bfloat16* __restrict__ Ahi, const __nv_bfloat16* __restrict__ Alo,
    const __nv_bfloat16* __restrict__ Bhi, const __nv_bfloat16* __restrict__ Blo,
    const float* __restrict__ bias, float* __restrict__ C)
{
    __shared__ __nv_bfloat16 sAhi[128 * LDSG];
    __shared__ __nv_bfloat16 sAlo[128 * LDSG];
    __shared__ __nv_bfloat16 sBhi[64 * LDSG];
    __shared__ __nv_bfloat16 sBlo[64 * LDSG];

    const int tid = threadIdx.x;
    const int wid = tid >> 5;
    const int lane = tid & 31;
    const int warp_m = wid & 3;
    const int warp_n = wid >> 2;
    const int m0 = blockIdx.y * 128;
    const int n0 = blockIdx.x * 64;

    float acc[2][4][4];
#pragma unroll
    for (int i = 0; i < 2; i++)
#pragma unroll
        for (int j = 0; j < 4; j++)
#pragma unroll
            for (int l = 0; l < 4; l++) acc[i][j][l] = 0.f;

    const int arow = tid >> 2;
    const int acol = (tid & 3) * 8;

    const int lr  = lane & 15;
    const int lkq = (lane >> 4) * 8;
    const int br  = lane & 7;
    const int bkq = ((lane >> 3) & 1) * 8;

    for (int kc = 0; kc < GK; kc += BKC) {
        const size_t aoff0 = (size_t)(m0 + arow) * GK + kc + acol;
        const size_t aoff1 = (size_t)(m0 + 64 + arow) * GK + kc + acol;
        const size_t boff  = (size_t)(n0 + arow) * GK + kc + acol;
        *(uint4*)&sAhi[arow * LDSG + acol]        = *(const uint4*)(Ahi + aoff0);
        *(uint4*)&sAhi[(arow + 64) * LDSG + acol] = *(const uint4*)(Ahi + aoff1);
        *(uint4*)&sAlo[arow * LDSG + acol]        = *(const uint4*)(Alo + aoff0);
        *(uint4*)&sAlo[(arow + 64) * LDSG + acol] = *(const uint4*)(Alo + aoff1);
        *(uint4*)&sBhi[arow * LDSG + acol]        = *(const uint4*)(Bhi + boff);
        *(uint4*)&sBlo[arow * LDSG + acol]        = *(const uint4*)(Blo + boff);
        __syncthreads();

#pragma unroll
        for (int ks = 0; ks < 2; ks++) {
            const int kb = ks * 16;
            uint32_t ah[2][4], al[2][4];
#pragma unroll
            for (int mt = 0; mt < 2; mt++) {
                int row = warp_m * 32 + mt * 16 + lr;
                ldmatrix_x4(ah[mt], smem_u32(&sAhi[row * LDSG + kb + lkq]));
                ldmatrix_x4(al[mt], smem_u32(&sAlo[row * LDSG + kb + lkq]));
            }
            uint32_t bh[4][2], bl[4][2];
#pragma unroll
            for (int nt = 0; nt < 4; nt++) {
                int row = warp_n * 32 + nt * 8 + br;
                ldmatrix_x2(bh[nt], smem_u32(&sBhi[row * LDSG + kb + bkq]));
                ldmatrix_x2(bl[nt], smem_u32(&sBlo[row * LDSG + kb + bkq]));
            }
#pragma unroll
            for (int mt = 0; mt < 2; mt++)
#pragma unroll
                for (int nt = 0; nt < 4; nt++) {
                    mma_bf16(acc[mt][nt], ah[mt], bh[nt]);
                    mma_bf16(acc[mt][nt], ah[mt], bl[nt]);
                    mma_bf16(acc[mt][nt], al[mt], bh[nt]);
                }
        }
        __syncthreads();
    }

    const int g = lane >> 2;
    const int t = lane & 3;
#pragma unroll
    for (int mt = 0; mt < 2; mt++) {
        const int row0 = m0 + warp_m * 32 + mt * 16 + g;
#pragma unroll
        for (int nt = 0; nt < 4; nt++) {
            const int col = n0 + warp_n * 32 + nt * 8 + t * 2;
            float2 b2 = *(const float2*)(bias + col);
            float2 o0, o1;
            o0.x = acc[mt][nt][0] + b2.x;
            o0.y = acc[mt][nt][1] + b2.y;
            o1.x = acc[mt][nt][2] + b2.x;
            o1.y = acc[mt][nt][3] + b2.y;
            *(float2*)(C + (size_t)row0 * GN + col)       = o0;
            *(float2*)(C + (size_t)(row0 + 8) * GN + col) = o1;
        }
    }
}

// ---------------------------------------------------------------------------
// Flash attention fp32, causal — 2 threads per query row (lane pair tid^1).
// 256 threads = 128 rows/block. Each thread: half the depth (32 dims).
// Key tile BN=16. Score = own-half partial dot + shfl_xor(partial, 1).
// regs ~110 -> 2 CTAs/SM = 16 warps (vs 8 before).
// ---------------------------------------------------------------------------
#define FB_BN 16

__global__ __launch_bounds__(256, 2) void flash_attn2(
    const float* __restrict__ Q, const float* __restrict__ K,
    const float* __restrict__ V, float* __restrict__ O)
{
    __shared__ float Ks[FB_BN][DEPTH];
    __shared__ float Vs[FB_BN][DEPTH];

    const int tid  = threadIdx.x;
    const int rloc = tid >> 1;          // 0..127 local row
    const int half = tid & 1;           // depth half
    const int bh = blockIdx.y;
    const int b  = bh >> 4;
    const int h  = bh & 15;
    const int q0 = (15 - (int)blockIdx.x) * 128;   // heavy blocks first
    const int srow = q0 + rloc;

    const float* qptr = Q + (size_t)(b * SEQ + srow) * D_MODEL + h * DEPTH + half * 32;
    float4 qr[8];
#pragma unroll
    for (int i = 0; i < 8; i++) qr[i] = *(const float4*)(qptr + i * 4);

    float4 acc[8];
#pragma unroll
    for (int i = 0; i < 8; i++) acc[i] = make_float4(0.f, 0.f, 0.f, 0.f);
    float mrun = -1e30f, lrun = 0.f;

    const float scale = 0.125f;   // 1/sqrt(64)
    const int ntiles = q0 / FB_BN + 128 / FB_BN;   // keys [0, q0+127]

    // tile loader: 16 rows x 16 float4 per array; 256 threads load 1 K + 1 V each
    const int lrow = tid >> 4;       // 0..15
    const int lc4  = tid & 15;       // 0..15
    const size_t kvbase = (size_t)(b * SEQ) * D_MODEL + h * DEPTH + lc4 * 4;

    for (int t = 0; t < ntiles; t++) {
        const int k0 = t * FB_BN;
        size_t goff = kvbase + (size_t)(k0 + lrow) * D_MODEL;
        *(float4*)(&Ks[lrow][lc4 * 4]) = *(const float4*)(K + goff);
        *(float4*)(&Vs[lrow][lc4 * 4]) = *(const float4*)(V + goff);
        __syncthreads();

        // scores: partial dot over own 32 dims, combine with pair lane
        float s[FB_BN];
        float tmax = -1e30f;
#pragma unroll
        for (int j = 0; j < FB_BN; j++) {
            const float* kp = &Ks[j][half * 32];
            float s0 = 0.f, s1 = 0.f, s2 = 0.f, s3 = 0.f;
#pragma unroll
            for (int d4 = 0; d4 < 8; d4++) {
                float4 kv = *(const float4*)(kp + d4 * 4);
                s0 = fmaf(qr[d4].x, kv.x, s0);
                s1 = fmaf(qr[d4].y, kv.y, s1);
                s2 = fmaf(qr[d4].z, kv.z, s2);
                s3 = fmaf(qr[d4].w, kv.w, s3);
            }
            float part = (s0 + s1) + (s2 + s3);
            float sj = (part + __shfl_xor_sync(0xffffffff, part, 1)) * scale;
            if (k0 + j > srow) sj = -1e30f;
            s[j] = sj;
            tmax = fmaxf(tmax, sj);
        }

        const float mnew = fmaxf(mrun, tmax);
        const float corr = __expf(mrun - mnew);
        lrun *= corr;
#pragma unroll
        for (int i = 0; i < 8; i++) {
            acc[i].x *= corr; acc[i].y *= corr;
            acc[i].z *= corr; acc[i].w *= corr;
        }

#pragma unroll
        for (int j = 0; j < FB_BN; j++) {
            float p = __expf(s[j] - mnew);
            lrun += p;
            const float* vp = &Vs[j][half * 32];
#pragma unroll
            for (int d4 = 0; d4 < 8; d4++) {
                float4 vv = *(const float4*)(vp + d4 * 4);
                acc[d4].x = fmaf(p, vv.x, acc[d4].x);
                acc[d4].y = fmaf(p, vv.y, acc[d4].y);
                acc[d4].z = fmaf(p, vv.z, acc[d4].z);
                acc[d4].w = fmaf(p, vv.w, acc[d4].w);
            }
        }
        mrun = mnew;
        __syncthreads();
    }

    const float inv = 1.f / lrun;
    float* optr = O + (size_t)(b * SEQ + srow) * D_MODEL + h * DEPTH + half * 32;
#pragma unroll
    for (int i = 0; i < 8; i++) {
        float4 o;
        o.x = acc[i].x * inv; o.y = acc[i].y * inv;
        o.z = acc[i].z * inv; o.w = acc[i].w * inv;
        *(float4*)(optr + i * 4) = o;
    }
}

// ---------------------------------------------------------------------------
// Launch: 0:v 1:k 2:q 3:mask 4:wq_w 5:wq_b 6:wk_w 7:wk_b 8:wv_w 9:wv_b
//         10:dense_w 11:dense_b
// ---------------------------------------------------------------------------
extern "C" void kernel_launch(void* const* d_in, const int* in_sizes, int n_in,
                              void* d_out, int out_size)
{
    const float* v       = (const float*)d_in[0];
    const float* k       = (const float*)d_in[1];
    const float* q       = (const float*)d_in[2];
    const float* wq_w    = (const float*)d_in[4];
    const float* wq_b    = (const float*)d_in[5];
    const float* wk_w    = (const float*)d_in[6];
    const float* wk_b    = (const float*)d_in[7];
    const float* wv_w    = (const float*)d_in[8];
    const float* wv_b    = (const float*)d_in[9];
    const float* dense_w = (const float*)d_in[10];
    const float* dense_b = (const float*)d_in[11];
    float* out = (float*)d_out;

    float *gq, *gk, *gv, *go;
    __nv_bfloat16 *ahi, *alo, *whi, *wlo;
    cudaGetSymbolAddress((void**)&gq, g_q);
    cudaGetSymbolAddress((void**)&gk, g_k);
    cudaGetSymbolAddress((void**)&gv, g_v);
    cudaGetSymbolAddress((void**)&go, g_o);
    cudaGetSymbolAddress((void**)&ahi, s_ahi);
    cudaGetSymbolAddress((void**)&alo, s_alo);
    cudaGetSymbolAddress((void**)&whi, s_whi);
    cudaGetSymbolAddress((void**)&wlo, s_wlo);

    const int nact4 = NROWS * D_MODEL / 4;
    const int nw4   = D_MODEL * D_MODEL / 4;
    dim3 ggrid(GN / 64, NROWS / 128);   // (16, 32)

    split_bf16<<<nact4 / 256, 256>>>(q, ahi, alo, nact4);
    split_bf16<<<nw4 / 256, 256>>>(wq_w, whi, wlo, nw4);
    gemm_mma_split<<<ggrid, 256>>>(ahi, alo, whi, wlo, wq_b, gq);

    split_bf16<<<nact4 / 256, 256>>>(k, ahi, alo, nact4);
    split_bf16<<<nw4 / 256, 256>>>(wk_w, whi, wlo, nw4);
    gemm_mma_split<<<ggrid, 256>>>(ahi, alo, whi, wlo, wk_b, gk);

    split_bf16<<<nact4 / 256, 256>>>(v, ahi, alo, nact4);
    split_bf16<<<nw4 / 256, 256>>>(wv_w, whi, wlo, nw4);
    gemm_mma_split<<<ggrid, 256>>>(ahi, alo, whi, wlo, wv_b, gv);

    dim3 fa_grid(SEQ / 128, BATCH * NHEADS);   // (16, 32)
    flash_attn2<<<fa_grid, 256>>>(gq, gk, gv, go);

    split_bf16<<<nact4 / 256, 256>>>(go, ahi, alo, nact4);
    split_bf16<<<nw4 / 256, 256>>>(dense_w, whi, wlo, nw4);
    gemm_mma_split<<<ggrid, 256>>>(ahi, alo, whi, wlo, dense_b, out);
}

// round 8
// speedup vs baseline: 1.1700x; 1.1700x over previous
#include <cuda_runtime.h>
#include <cuda_bf16.h>
#include <cstdint>
#include <math.h>

#define D_MODEL 1024
#define NHEADS  16
#define DEPTH   64
#define BATCH   2
#define SEQ     2048
#define NROWS   (BATCH * SEQ)   // 4096

// ---------------- scratch (no allocation allowed) ----------------
__device__ float g_q[NROWS * D_MODEL];
__device__ float g_k[NROWS * D_MODEL];
__device__ float g_v[NROWS * D_MODEL];
__device__ float g_o[NROWS * D_MODEL];
__device__ __nv_bfloat16 s_ahi[NROWS * D_MODEL];
__device__ __nv_bfloat16 s_alo[NROWS * D_MODEL];
__device__ __nv_bfloat16 s_whi[D_MODEL * D_MODEL];
__device__ __nv_bfloat16 s_wlo[D_MODEL * D_MODEL];

// ---------------- helpers ----------------
__device__ __forceinline__ uint32_t smem_u32(const void* p) {
    uint32_t a;
    asm("{ .reg .u64 t; cvta.to.shared.u64 t, %1; cvt.u32.u64 %0, t; }" : "=r"(a) : "l"(p));
    return a;
}
__device__ __forceinline__ void ldmatrix_x4(uint32_t* r, uint32_t addr) {
    asm volatile("ldmatrix.sync.aligned.m8n8.x4.shared.b16 {%0,%1,%2,%3}, [%4];"
                 : "=r"(r[0]), "=r"(r[1]), "=r"(r[2]), "=r"(r[3]) : "r"(addr));
}
__device__ __forceinline__ void ldmatrix_x2(uint32_t* r, uint32_t addr) {
    asm volatile("ldmatrix.sync.aligned.m8n8.x2.shared.b16 {%0,%1}, [%2];"
                 : "=r"(r[0]), "=r"(r[1]) : "r"(addr));
}
__device__ __forceinline__ void mma_bf16(float* c, const uint32_t* a, const uint32_t* b) {
    asm volatile(
        "mma.sync.aligned.m16n8k16.row.col.f32.bf16.bf16.f32 "
        "{%0,%1,%2,%3}, {%4,%5,%6,%7}, {%8,%9}, {%0,%1,%2,%3};"
        : "+f"(c[0]), "+f"(c[1]), "+f"(c[2]), "+f"(c[3])
        : "r"(a[0]), "r"(a[1]), "r"(a[2]), "r"(a[3]), "r"(b[0]), "r"(b[1]));
}
__device__ __forceinline__ void split_pack(float x, float y, uint32_t& hi, uint32_t& lo) {
    __nv_bfloat162 h = __floats2bfloat162_rn(x, y);
    float hx = __bfloat162float(__low2bfloat16(h));
    float hy = __bfloat162float(__high2bfloat16(h));
    __nv_bfloat162 l = __floats2bfloat162_rn(x - hx, y - hy);
    hi = *(uint32_t*)&h;
    lo = *(uint32_t*)&l;
}

// ---------------------------------------------------------------------------
// split fp32 -> (hi, lo) bf16 pair
// ---------------------------------------------------------------------------
__global__ __launch_bounds__(256) void split_bf16(
    const float* __restrict__ x, __nv_bfloat16* __restrict__ hi,
    __nv_bfloat16* __restrict__ lo, int n4)
{
    int i = blockIdx.x * blockDim.x + threadIdx.x;
    if (i >= n4) return;
    float4 v = ((const float4*)x)[i];
    uint32_t h0, l0, h1, l1;
    split_pack(v.x, v.y, h0, l0);
    split_pack(v.z, v.w, h1, l1);
    ((uint32_t*)hi)[2 * i]     = h0;
    ((uint32_t*)hi)[2 * i + 1] = h1;
    ((uint32_t*)lo)[2 * i]     = l0;
    ((uint32_t*)lo)[2 * i + 1] = l1;
}

// ---------------------------------------------------------------------------
// mma.sync split-bf16 GEMM-NT: C[M,N] = A[M,K] @ W[N,K]^T + bias  (validated)
// ---------------------------------------------------------------------------
#define GK 1024
#define GN 1024
#define BKC 32
#define LDSG 40

__global__ __launch_bounds__(256, 2) void gemm_mma_split(
    const __nv_bfloat16* __restrict__ Ahi, const __nv_bfloat16* __restrict__ Alo,
    const __nv_bfloat16* __restrict__ Bhi, const __nv_bfloat16* __restrict__ Blo,
    const float* __restrict__ bias, float* __restrict__ C)
{
    __shared__ __nv_bfloat16 sAhi[128 * LDSG];
    __shared__ __nv_bfloat16 sAlo[128 * LDSG];
    __shared__ __nv_bfloat16 sBhi[64 * LDSG];
    __shared__ __nv_bfloat16 sBlo[64 * LDSG];

    const int tid = threadIdx.x;
    const int wid = tid >> 5;
    const int lane = tid & 31;
    const int warp_m = wid & 3;
    const int warp_n = wid >> 2;
    const int m0 = blockIdx.y * 128;
    const int n0 = blockIdx.x * 64;

    float acc[2][4][4];
#pragma unroll
    for (int i = 0; i < 2; i++)
#pragma unroll
        for (int j = 0; j < 4; j++)
#pragma unroll
            for (int l = 0; l < 4; l++) acc[i][j][l] = 0.f;

    const int arow = tid >> 2;
    const int acol = (tid & 3) * 8;

    const int lr  = lane & 15;
    const int lkq = (lane >> 4) * 8;
    const int br  = lane & 7;
    const int bkq = ((lane >> 3) & 1) * 8;

    for (int kc = 0; kc < GK; kc += BKC) {
        const size_t aoff0 = (size_t)(m0 + arow) * GK + kc + acol;
        const size_t aoff1 = (size_t)(m0 + 64 + arow) * GK + kc + acol;
        const size_t boff  = (size_t)(n0 + arow) * GK + kc + acol;
        *(uint4*)&sAhi[arow * LDSG + acol]        = *(const uint4*)(Ahi + aoff0);
        *(uint4*)&sAhi[(arow + 64) * LDSG + acol] = *(const uint4*)(Ahi + aoff1);
        *(uint4*)&sAlo[arow * LDSG + acol]        = *(const uint4*)(Alo + aoff0);
        *(uint4*)&sAlo[(arow + 64) * LDSG + acol] = *(const uint4*)(Alo + aoff1);
        *(uint4*)&sBhi[arow * LDSG + acol]        = *(const uint4*)(Bhi + boff);
        *(uint4*)&sBlo[arow * LDSG + acol]        = *(const uint4*)(Blo + boff);
        __syncthreads();

#pragma unroll
        for (int ks = 0; ks < 2; ks++) {
            const int kb = ks * 16;
            uint32_t ah[2][4], al[2][4];
#pragma unroll
            for (int mt = 0; mt < 2; mt++) {
                int row = warp_m * 32 + mt * 16 + lr;
                ldmatrix_x4(ah[mt], smem_u32(&sAhi[row * LDSG + kb + lkq]));
                ldmatrix_x4(al[mt], smem_u32(&sAlo[row * LDSG + kb + lkq]));
            }
            uint32_t bh[4][2], bl[4][2];
#pragma unroll
            for (int nt = 0; nt < 4; nt++) {
                int row = warp_n * 32 + nt * 8 + br;
                ldmatrix_x2(bh[nt], smem_u32(&sBhi[row * LDSG + kb + bkq]));
                ldmatrix_x2(bl[nt], smem_u32(&sBlo[row * LDSG + kb + bkq]));
            }
#pragma unroll
            for (int mt = 0; mt < 2; mt++)
#pragma unroll
                for (int nt = 0; nt < 4; nt++) {
                    mma_bf16(acc[mt][nt], ah[mt], bh[nt]);
                    mma_bf16(acc[mt][nt], ah[mt], bl[nt]);
                    mma_bf16(acc[mt][nt], al[mt], bh[nt]);
                }
        }
        __syncthreads();
    }

    const int g = lane >> 2;
    const int t = lane & 3;
#pragma unroll
    for (int mt = 0; mt < 2; mt++) {
        const int row0 = m0 + warp_m * 32 + mt * 16 + g;
#pragma unroll
        for (int nt = 0; nt < 4; nt++) {
            const int col = n0 + warp_n * 32 + nt * 8 + t * 2;
            float2 b2 = *(const float2*)(bias + col);
            float2 o0, o1;
            o0.x = acc[mt][nt][0] + b2.x;
            o0.y = acc[mt][nt][1] + b2.y;
            o1.x = acc[mt][nt][2] + b2.x;
            o1.y = acc[mt][nt][3] + b2.y;
            *(float2*)(C + (size_t)row0 * GN + col)       = o0;
            *(float2*)(C + (size_t)(row0 + 8) * GN + col) = o1;
        }
    }
}

// ---------------------------------------------------------------------------
// Flash attention fp32, causal — 4 q-rows per lane-quad, 16 depth dims/lane.
// Each loaded K/V slice (64B) is reused for 4 rows -> smem traffic /4.
// Scores completed via quad butterfly (shfl_xor 1,2). Softmax in 8-key chunks.
// 128 threads cover 128 q-rows per block.
// ---------------------------------------------------------------------------
#define FC_BN 32

__global__ __launch_bounds__(128, 2) void flash_attn4(
    const float* __restrict__ Q, const float* __restrict__ K,
    const float* __restrict__ V, float* __restrict__ O)
{
    __shared__ float Ks[FC_BN][DEPTH];
    __shared__ float Vs[FC_BN][DEPTH];

    const int tid  = threadIdx.x;
    const int quad = tid >> 2;          // 0..31 -> 4 rows each
    const int sub  = tid & 3;           // depth slice
    const int ds   = sub * 16;
    const int bh = blockIdx.y;
    const int b  = bh >> 4;
    const int h  = bh & 15;
    const int q0 = (15 - (int)blockIdx.x) * 128;   // heavy blocks first
    const int rowbase = q0 + quad * 4;

    const float* qptr = Q + (size_t)(b * SEQ + rowbase) * D_MODEL + h * DEPTH + ds;
    float4 qr[4][4];
#pragma unroll
    for (int i = 0; i < 4; i++)
#pragma unroll
        for (int d = 0; d < 4; d++)
            qr[i][d] = *(const float4*)(qptr + (size_t)i * D_MODEL + d * 4);

    float4 acc[4][4];
#pragma unroll
    for (int i = 0; i < 4; i++)
#pragma unroll
        for (int d = 0; d < 4; d++) acc[i][d] = make_float4(0.f, 0.f, 0.f, 0.f);
    float m[4] = {-1e30f, -1e30f, -1e30f, -1e30f};
    float l[4] = {0.f, 0.f, 0.f, 0.f};

    const float scale = 0.125f;   // 1/sqrt(64)
    const int ntiles = q0 / FC_BN + 128 / FC_BN;   // keys [0, q0+127]

    // loader: 32 rows x 16 float4 x2 arrays; 128 threads -> 4 per array
    const int lrow = tid >> 4;       // base row 0..7 step 8
    const int lc4  = tid & 15;
    const size_t kvbase = (size_t)(b * SEQ) * D_MODEL + h * DEPTH + lc4 * 4;

    for (int t = 0; t < ntiles; t++) {
        const int k0 = t * FC_BN;
        __syncthreads();
#pragma unroll
        for (int i = 0; i < 4; i++) {
            int row = lrow + i * 8;
            size_t goff = kvbase + (size_t)(k0 + row) * D_MODEL;
            *(float4*)(&Ks[row][lc4 * 4]) = *(const float4*)(K + goff);
            *(float4*)(&Vs[row][lc4 * 4]) = *(const float4*)(V + goff);
        }
        __syncthreads();

#pragma unroll
        for (int sc = 0; sc < 4; sc++) {
            const int jb = sc * 8;
            float p[4][8];

            // ---- scores for 8 keys x 4 rows ----
#pragma unroll
            for (int j = 0; j < 8; j++) {
                const int jj = jb + j;
                const float* kp = &Ks[jj][ds];
                float4 kv0 = *(const float4*)(kp + 0);
                float4 kv1 = *(const float4*)(kp + 4);
                float4 kv2 = *(const float4*)(kp + 8);
                float4 kv3 = *(const float4*)(kp + 12);
                float pi[4];
#pragma unroll
                for (int i = 0; i < 4; i++) {
                    float s0 = qr[i][0].x * kv0.x + qr[i][0].y * kv0.y
                             + qr[i][0].z * kv0.z + qr[i][0].w * kv0.w;
                    float s1 = qr[i][1].x * kv1.x + qr[i][1].y * kv1.y
                             + qr[i][1].z * kv1.z + qr[i][1].w * kv1.w;
                    float s2 = qr[i][2].x * kv2.x + qr[i][2].y * kv2.y
                             + qr[i][2].z * kv2.z + qr[i][2].w * kv2.w;
                    float s3 = qr[i][3].x * kv3.x + qr[i][3].y * kv3.y
                             + qr[i][3].z * kv3.z + qr[i][3].w * kv3.w;
                    pi[i] = (s0 + s1) + (s2 + s3);
                }
                // quad butterfly: all 4 lanes get full dot for all 4 rows
#pragma unroll
                for (int i = 0; i < 4; i++) {
                    pi[i] += __shfl_xor_sync(0xffffffff, pi[i], 1);
                    pi[i] += __shfl_xor_sync(0xffffffff, pi[i], 2);
                }
#pragma unroll
                for (int i = 0; i < 4; i++)
                    p[i][j] = (k0 + jj > rowbase + i) ? -1e30f : pi[i] * scale;
            }

            // ---- online softmax update (per row) ----
#pragma unroll
            for (int i = 0; i < 4; i++) {
                float cm = p[i][0];
#pragma unroll
                for (int j = 1; j < 8; j++) cm = fmaxf(cm, p[i][j]);
                const float mn = fmaxf(m[i], cm);
                const float cr = __expf(m[i] - mn);
                m[i] = mn;
                l[i] *= cr;
#pragma unroll
                for (int d = 0; d < 4; d++) {
                    acc[i][d].x *= cr; acc[i][d].y *= cr;
                    acc[i][d].z *= cr; acc[i][d].w *= cr;
                }
#pragma unroll
                for (int j = 0; j < 8; j++) {
                    p[i][j] = __expf(p[i][j] - mn);
                    l[i] += p[i][j];
                }
            }

            // ---- PV ----
#pragma unroll
            for (int j = 0; j < 8; j++) {
                const int jj = jb + j;
                const float* vp = &Vs[jj][ds];
                float4 vv0 = *(const float4*)(vp + 0);
                float4 vv1 = *(const float4*)(vp + 4);
                float4 vv2 = *(const float4*)(vp + 8);
                float4 vv3 = *(const float4*)(vp + 12);
#pragma unroll
                for (int i = 0; i < 4; i++) {
                    const float pj = p[i][j];
                    acc[i][0].x = fmaf(pj, vv0.x, acc[i][0].x);
                    acc[i][0].y = fmaf(pj, vv0.y, acc[i][0].y);
                    acc[i][0].z = fmaf(pj, vv0.z, acc[i][0].z);
                    acc[i][0].w = fmaf(pj, vv0.w, acc[i][0].w);
                    acc[i][1].x = fmaf(pj, vv1.x, acc[i][1].x);
                    acc[i][1].y = fmaf(pj, vv1.y, acc[i][1].y);
                    acc[i][1].z = fmaf(pj, vv1.z, acc[i][1].z);
                    acc[i][1].w = fmaf(pj, vv1.w, acc[i][1].w);
                    acc[i][2].x = fmaf(pj, vv2.x, acc[i][2].x);
                    acc[i][2].y = fmaf(pj, vv2.y, acc[i][2].y);
                    acc[i][2].z = fmaf(pj, vv2.z, acc[i][2].z);
                    acc[i][2].w = fmaf(pj, vv2.w, acc[i][2].w);
                    acc[i][3].x = fmaf(pj, vv3.x, acc[i][3].x);
                    acc[i][3].y = fmaf(pj, vv3.y, acc[i][3].y);
                    acc[i][3].z = fmaf(pj, vv3.z, acc[i][3].z);
                    acc[i][3].w = fmaf(pj, vv3.w, acc[i][3].w);
                }
            }
        }
    }

    // ---- finalize ----
    float* optr = O + (size_t)(b * SEQ + rowbase) * D_MODEL + h * DEPTH + ds;
#pragma unroll
    for (int i = 0; i < 4; i++) {
        const float inv = 1.f / l[i];
#pragma unroll
        for (int d = 0; d < 4; d++) {
            float4 o;
            o.x = acc[i][d].x * inv; o.y = acc[i][d].y * inv;
            o.z = acc[i][d].z * inv; o.w = acc[i][d].w * inv;
            *(float4*)(optr + (size_t)i * D_MODEL + d * 4) = o;
        }
    }
}

// ---------------------------------------------------------------------------
// Launch: 0:v 1:k 2:q 3:mask 4:wq_w 5:wq_b 6:wk_w 7:wk_b 8:wv_w 9:wv_b
//         10:dense_w 11:dense_b
// ---------------------------------------------------------------------------
extern "C" void kernel_launch(void* const* d_in, const int* in_sizes, int n_in,
                              void* d_out, int out_size)
{
    const float* v       = (const float*)d_in[0];
    const float* k       = (const float*)d_in[1];
    const float* q       = (const float*)d_in[2];
    const float* wq_w    = (const float*)d_in[4];
    const float* wq_b    = (const float*)d_in[5];
    const float* wk_w    = (const float*)d_in[6];
    const float* wk_b    = (const float*)d_in[7];
    const float* wv_w    = (const float*)d_in[8];
    const float* wv_b    = (const float*)d_in[9];
    const float* dense_w = (const float*)d_in[10];
    const float* dense_b = (const float*)d_in[11];
    float* out = (float*)d_out;

    float *gq, *gk, *gv, *go;
    __nv_bfloat16 *ahi, *alo, *whi, *wlo;
    cudaGetSymbolAddress((void**)&gq, g_q);
    cudaGetSymbolAddress((void**)&gk, g_k);
    cudaGetSymbolAddress((void**)&gv, g_v);
    cudaGetSymbolAddress((void**)&go, g_o);
    cudaGetSymbolAddress((void**)&ahi, s_ahi);
    cudaGetSymbolAddress((void**)&alo, s_alo);
    cudaGetSymbolAddress((void**)&whi, s_whi);
    cudaGetSymbolAddress((void**)&wlo, s_wlo);

    const int nact4 = NROWS * D_MODEL / 4;
    const int nw4   = D_MODEL * D_MODEL / 4;
    dim3 ggrid(GN / 64, NROWS / 128);   // (16, 32)

    split_bf16<<<nact4 / 256, 256>>>(q, ahi, alo, nact4);
    split_bf16<<<nw4 / 256, 256>>>(wq_w, whi, wlo, nw4);
    gemm_mma_split<<<ggrid, 256>>>(ahi, alo, whi, wlo, wq_b, gq);

    split_bf16<<<nact4 / 256, 256>>>(k, ahi, alo, nact4);
    split_bf16<<<nw4 / 256, 256>>>(wk_w, whi, wlo, nw4);
    gemm_mma_split<<<ggrid, 256>>>(ahi, alo, whi, wlo, wk_b, gk);

    split_bf16<<<nact4 / 256, 256>>>(v, ahi, alo, nact4);
    split_bf16<<<nw4 / 256, 256>>>(wv_w, whi, wlo, nw4);
    gemm_mma_split<<<ggrid, 256>>>(ahi, alo, whi, wlo, wv_b, gv);

    dim3 fa_grid(SEQ / 128, BATCH * NHEADS);   // (16, 32)
    flash_attn4<<<fa_grid, 128>>>(gq, gk, gv, go);

    split_bf16<<<nact4 / 256, 256>>>(go, ahi, alo, nact4);
    split_bf16<<<nw4 / 256, 256>>>(dense_w, whi, wlo, nw4);
    gemm_mma_split<<<ggrid, 256>>>(ahi, alo, whi, wlo, dense_b, out);
}

// round 11
// speedup vs baseline: 2.2290x; 1.9051x over previous
#include <cuda_runtime.h>
#include <cuda_bf16.h>
#include <cstdint>
#include <math.h>

#define D_MODEL 1024
#define NHEADS  16
#define DEPTH   64
#define BATCH   2
#define SEQ     2048
#define NROWS   (BATCH * SEQ)   // 4096

// ---------------- scratch (no allocation allowed) ----------------
__device__ float g_q[NROWS * D_MODEL];
__device__ float g_k[NROWS * D_MODEL];
__device__ float g_v[NROWS * D_MODEL];
__device__ float g_o[NROWS * D_MODEL];
__device__ __nv_bfloat16 s_ahi[NROWS * D_MODEL];
__device__ __nv_bfloat16 s_alo[NROWS * D_MODEL];
__device__ __nv_bfloat16 s_whi[D_MODEL * D_MODEL];
__device__ __nv_bfloat16 s_wlo[D_MODEL * D_MODEL];
__device__ __nv_bfloat16 s_qhi[NROWS * D_MODEL];
__device__ __nv_bfloat16 s_qlo[NROWS * D_MODEL];
__device__ __nv_bfloat16 s_khi[NROWS * D_MODEL];
__device__ __nv_bfloat16 s_klo[NROWS * D_MODEL];
__device__ __nv_bfloat16 s_vhi[NROWS * D_MODEL];
__device__ __nv_bfloat16 s_vlo[NROWS * D_MODEL];

// ---------------- helpers ----------------
__device__ __forceinline__ uint32_t smem_u32(const void* p) {
    uint32_t a;
    asm("{ .reg .u64 t; cvta.to.shared.u64 t, %1; cvt.u32.u64 %0, t; }" : "=r"(a) : "l"(p));
    return a;
}
__device__ __forceinline__ void ldmatrix_x4(uint32_t* r, uint32_t addr) {
    asm volatile("ldmatrix.sync.aligned.m8n8.x4.shared.b16 {%0,%1,%2,%3}, [%4];"
                 : "=r"(r[0]), "=r"(r[1]), "=r"(r[2]), "=r"(r[3]) : "r"(addr));
}
__device__ __forceinline__ void ldmatrix_x2(uint32_t* r, uint32_t addr) {
    asm volatile("ldmatrix.sync.aligned.m8n8.x2.shared.b16 {%0,%1}, [%2];"
                 : "=r"(r[0]), "=r"(r[1]) : "r"(addr));
}
__device__ __forceinline__ void mma_bf16(float* c, const uint32_t* a, const uint32_t* b) {
    asm volatile(
        "mma.sync.aligned.m16n8k16.row.col.f32.bf16.bf16.f32 "
        "{%0,%1,%2,%3}, {%4,%5,%6,%7}, {%8,%9}, {%0,%1,%2,%3};"
        : "+f"(c[0]), "+f"(c[1]), "+f"(c[2]), "+f"(c[3])
        : "r"(a[0]), "r"(a[1]), "r"(a[2]), "r"(a[3]), "r"(b[0]), "r"(b[1]));
}
__device__ __forceinline__ void split_pack(float x, float y, uint32_t& hi, uint32_t& lo) {
    __nv_bfloat162 h = __floats2bfloat162_rn(x, y);
    float hx = __bfloat162float(__low2bfloat16(h));
    float hy = __bfloat162float(__high2bfloat16(h));
    __nv_bfloat162 l = __floats2bfloat162_rn(x - hx, y - hy);
    hi = *(uint32_t*)&h;
    lo = *(uint32_t*)&l;
}

// ---------------------------------------------------------------------------
// split fp32 -> (hi, lo) bf16 pair
// ---------------------------------------------------------------------------
__global__ __launch_bounds__(256) void split_bf16(
    const float* __restrict__ x, __nv_bfloat16* __restrict__ hi,
    __nv_bfloat16* __restrict__ lo, int n4)
{
    int i = blockIdx.x * blockDim.x + threadIdx.x;
    if (i >= n4) return;
    float4 v = ((const float4*)x)[i];
    uint32_t h0, l0, h1, l1;
    split_pack(v.x, v.y, h0, l0);
    split_pack(v.z, v.w, h1, l1);
    ((uint32_t*)hi)[2 * i]     = h0;
    ((uint32_t*)hi)[2 * i + 1] = h1;
    ((uint32_t*)lo)[2 * i]     = l0;
    ((uint32_t*)lo)[2 * i + 1] = l1;
}

// ---------------------------------------------------------------------------
// mma.sync split-bf16 GEMM-NT: C[M,N] = A[M,K] @ W[N,K]^T + bias  (validated)
// ---------------------------------------------------------------------------
#define GK 1024
#define GN 1024
#define BKC 32
#define LDSG 40

__global__ __launch_bounds__(256, 2) void gemm_mma_split(
    const __nv_bfloat16* __restrict__ Ahi, const __nv_bfloat16* __restrict__ Alo,
    const __nv_bfloat16* __restrict__ Bhi, const __nv_bfloat16* __restrict__ Blo,
    const float* __restrict__ bias, float* __restrict__ C)
{
    __shared__ __nv_bfloat16 sAhi[128 * LDSG];
    __shared__ __nv_bfloat16 sAlo[128 * LDSG];
    __shared__ __nv_bfloat16 sBhi[64 * LDSG];
    __shared__ __nv_bfloat16 sBlo[64 * LDSG];

    const int tid = threadIdx.x;
    const int wid = tid >> 5;
    const int lane = tid & 31;
    const int warp_m = wid & 3;
    const int warp_n = wid >> 2;
    const int m0 = blockIdx.y * 128;
    const int n0 = blockIdx.x * 64;

    float acc[2][4][4];
#pragma unroll
    for (int i = 0; i < 2; i++)
#pragma unroll
        for (int j = 0; j < 4; j++)
#pragma unroll
            for (int l = 0; l < 4; l++) acc[i][j][l] = 0.f;

    const int arow = tid >> 2;
    const int acol = (tid & 3) * 8;

    const int lr  = lane & 15;
    const int lkq = (lane >> 4) * 8;
    const int br  = lane & 7;
    const int bkq = ((lane >> 3) & 1) * 8;

    for (int kc = 0; kc < GK; kc += BKC) {
        const size_t aoff0 = (size_t)(m0 + arow) * GK + kc + acol;
        const size_t aoff1 = (size_t)(m0 + 64 + arow) * GK + kc + acol;
        const size_t boff  = (size_t)(n0 + arow) * GK + kc + acol;
        *(uint4*)&sAhi[arow * LDSG + acol]        = *(const uint4*)(Ahi + aoff0);
        *(uint4*)&sAhi[(arow + 64) * LDSG + acol] = *(const uint4*)(Ahi + aoff1);
        *(uint4*)&sAlo[arow * LDSG + acol]        = *(const uint4*)(Alo + aoff0);
        *(uint4*)&sAlo[(arow + 64) * LDSG + acol] = *(const uint4*)(Alo + aoff1);
        *(uint4*)&sBhi[arow * LDSG + acol]        = *(const uint4*)(Bhi + boff);
        *(uint4*)&sBlo[arow * LDSG + acol]        = *(const uint4*)(Blo + boff);
        __syncthreads();

#pragma unroll
        for (int ks = 0; ks < 2; ks++) {
            const int kb = ks * 16;
            uint32_t ah[2][4], al[2][4];
#pragma unroll
            for (int mt = 0; mt < 2; mt++) {
                int row = warp_m * 32 + mt * 16 + lr;
                ldmatrix_x4(ah[mt], smem_u32(&sAhi[row * LDSG + kb + lkq]));
                ldmatrix_x4(al[mt], smem_u32(&sAlo[row * LDSG + kb + lkq]));
            }
            uint32_t bh[4][2], bl[4][2];
#pragma unroll
            for (int nt = 0; nt < 4; nt++) {
                int row = warp_n * 32 + nt * 8 + br;
                ldmatrix_x2(bh[nt], smem_u32(&sBhi[row * LDSG + kb + bkq]));
                ldmatrix_x2(bl[nt], smem_u32(&sBlo[row * LDSG + kb + bkq]));
            }
#pragma unroll
            for (int mt = 0; mt < 2; mt++)
#pragma unroll
                for (int nt = 0; nt < 4; nt++) {
                    mma_bf16(acc[mt][nt], ah[mt], bh[nt]);
                    mma_bf16(acc[mt][nt], ah[mt], bl[nt]);
                    mma_bf16(acc[mt][nt], al[mt], bh[nt]);
                }
        }
        __syncthreads();
    }

    const int g = lane >> 2;
    const int t = lane & 3;
#pragma unroll
    for (int mt = 0; mt < 2; mt++) {
        const int row0 = m0 + warp_m * 32 + mt * 16 + g;
#pragma unroll
        for (int nt = 0; nt < 4; nt++) {
            const int col = n0 + warp_n * 32 + nt * 8 + t * 2;
            float2 b2 = *(const float2*)(bias + col);
            float2 o0, o1;
            o0.x = acc[mt][nt][0] + b2.x;
            o0.y = acc[mt][nt][1] + b2.y;
            o1.x = acc[mt][nt][2] + b2.x;
            o1.y = acc[mt][nt][3] + b2.y;
            *(float2*)(C + (size_t)row0 * GN + col)       = o0;
            *(float2*)(C + (size_t)(row0 + 8) * GN + col) = o1;
        }
    }
}

// ---------------------------------------------------------------------------
// Tensor-core flash attention, split-bf16, causal.  LDK FIXED: 40 -> 72.
// 256 thr = 8 warps; BM=128 q-rows (16/warp), key tile BN=64, depth 64.
// Q/K/VT tiles in dynamic smem (73728 B). All ldmatrix = GEMM-validated
// non-trans patterns; V pre-transposed to VT [depth][key] in smem.
// ---------------------------------------------------------------------------
#define LDK  72   // Q/K tile row stride in halves (64 data + 8 pad)
#define LDVT 72   // VT tile row stride (64 keys + 8 pad)
#define FOFF_QH 0
#define FOFF_QL 18432
#define FOFF_KH 36864
#define FOFF_KL 46080
#define FOFF_VTH 55296
#define FOFF_VTL 64512
#define FLASH_SMEM 73728

__global__ __launch_bounds__(256) void flash_mma(
    const __nv_bfloat16* __restrict__ Qhi, const __nv_bfloat16* __restrict__ Qlo,
    const __nv_bfloat16* __restrict__ Khi, const __nv_bfloat16* __restrict__ Klo,
    const __nv_bfloat16* __restrict__ Vhi, const __nv_bfloat16* __restrict__ Vlo,
    float* __restrict__ O)
{
    extern __shared__ char fsm[];
    __nv_bfloat16* sQh  = (__nv_bfloat16*)(fsm + FOFF_QH);
    __nv_bfloat16* sQl  = (__nv_bfloat16*)(fsm + FOFF_QL);
    __nv_bfloat16* sKh  = (__nv_bfloat16*)(fsm + FOFF_KH);
    __nv_bfloat16* sKl  = (__nv_bfloat16*)(fsm + FOFF_KL);
    __nv_bfloat16* sVTh = (__nv_bfloat16*)(fsm + FOFF_VTH);  // [depth][key]
    __nv_bfloat16* sVTl = (__nv_bfloat16*)(fsm + FOFF_VTL);

    const int tid  = threadIdx.x;
    const int wid  = tid >> 5;
    const int lane = tid & 31;
    const int bh = blockIdx.y;
    const int b  = bh >> 4;
    const int h  = bh & 15;
    const int q0 = (15 - (int)blockIdx.x) * 128;   // heavy blocks first
    const size_t base = (size_t)(b * SEQ) * D_MODEL + h * DEPTH;

    // ---- load Q tile (128 x 64, hi/lo) ----
#pragma unroll
    for (int i = 0; i < 4; i++) {
        int idx = tid + i * 256;          // 0..1023
        int row = idx >> 3;
        int c   = (idx & 7) * 8;
        size_t go = base + (size_t)(q0 + row) * D_MODEL + c;
        *(uint4*)&sQh[row * LDK + c] = *(const uint4*)(Qhi + go);
        *(uint4*)&sQl[row * LDK + c] = *(const uint4*)(Qlo + go);
    }
    __syncthreads();

    // ---- preload Q A-fragments (GEMM-validated x4 pattern) ----
    const int lr  = lane & 15;
    const int lkq = (lane >> 4) * 8;
    const int br  = lane & 7;
    const int bkq = ((lane >> 3) & 1) * 8;
    uint32_t qh[4][4], ql[4][4];
    const int qrow = wid * 16 + lr;
#pragma unroll
    for (int ks = 0; ks < 4; ks++) {
        ldmatrix_x4(qh[ks], smem_u32(&sQh[qrow * LDK + ks * 16 + lkq]));
        ldmatrix_x4(ql[ks], smem_u32(&sQl[qrow * LDK + ks * 16 + lkq]));
    }

    const int g = lane >> 2;
    const int t = lane & 3;
    float acc[8][4];
#pragma unroll
    for (int nt = 0; nt < 8; nt++)
#pragma unroll
        for (int j = 0; j < 4; j++) acc[nt][j] = 0.f;
    float m0 = -1e30f, m1 = -1e30f, l0 = 0.f, l1 = 0.f;

    const int r0g = q0 + wid * 16 + g;       // this thread's two q-rows
    const int r1g = r0g + 8;
    const int ntiles = q0 / 64 + 2;

    for (int tt = 0; tt < ntiles; tt++) {
        const int k0 = tt * 64;
        __syncthreads();
        // ---- load K tile [key][depth]; V transposed -> VT [depth][key] ----
#pragma unroll
        for (int i = 0; i < 2; i++) {
            int idx = tid + i * 256;         // 0..511
            int row = idx >> 3;              // key 0..63
            int c   = (idx & 7) * 8;         // depth base
            size_t go = base + (size_t)(k0 + row) * D_MODEL + c;
            *(uint4*)&sKh[row * LDK + c] = *(const uint4*)(Khi + go);
            *(uint4*)&sKl[row * LDK + c] = *(const uint4*)(Klo + go);
            uint4 vh4 = *(const uint4*)(Vhi + go);
            uint4 vl4 = *(const uint4*)(Vlo + go);
            const __nv_bfloat16* vh8 = (const __nv_bfloat16*)&vh4;
            const __nv_bfloat16* vl8 = (const __nv_bfloat16*)&vl4;
#pragma unroll
            for (int j = 0; j < 8; j++) {
                sVTh[(c + j) * LDVT + row] = vh8[j];
                sVTl[(c + j) * LDVT + row] = vl8[j];
            }
        }
        __syncthreads();

        // ---- QK^T (K B-frags: GEMM-validated x2 pattern) ----
        float c_[8][4];
#pragma unroll
        for (int nt = 0; nt < 8; nt++)
#pragma unroll
            for (int j = 0; j < 4; j++) c_[nt][j] = 0.f;

#pragma unroll
        for (int ks = 0; ks < 4; ks++) {
            const int kb = ks * 16;
#pragma unroll
            for (int nt = 0; nt < 8; nt++) {
                uint32_t kh[2], kl[2];
                int row = nt * 8 + br;
                ldmatrix_x2(kh, smem_u32(&sKh[row * LDK + kb + bkq]));
                ldmatrix_x2(kl, smem_u32(&sKl[row * LDK + kb + bkq]));
                mma_bf16(c_[nt], qh[ks], kh);
                mma_bf16(c_[nt], qh[ks], kl);
                mma_bf16(c_[nt], ql[ks], kh);
            }
        }

        // ---- scale + causal mask ----
#pragma unroll
        for (int nt = 0; nt < 8; nt++)
#pragma unroll
            for (int j = 0; j < 4; j++) c_[nt][j] *= 0.125f;

        if (k0 + 63 > q0 + wid * 16) {
#pragma unroll
            for (int nt = 0; nt < 8; nt++) {
                int col = k0 + nt * 8 + t * 2;
                if (col > r0g)     c_[nt][0] = -1e30f;
                if (col + 1 > r0g) c_[nt][1] = -1e30f;
                if (col > r1g)     c_[nt][2] = -1e30f;
                if (col + 1 > r1g) c_[nt][3] = -1e30f;
            }
        }

        // ---- online softmax ----
        float tm0 = -1e30f, tm1 = -1e30f;
#pragma unroll
        for (int nt = 0; nt < 8; nt++) {
            tm0 = fmaxf(tm0, fmaxf(c_[nt][0], c_[nt][1]));
            tm1 = fmaxf(tm1, fmaxf(c_[nt][2], c_[nt][3]));
        }
        tm0 = fmaxf(tm0, __shfl_xor_sync(0xffffffff, tm0, 1));
        tm0 = fmaxf(tm0, __shfl_xor_sync(0xffffffff, tm0, 2));
        tm1 = fmaxf(tm1, __shfl_xor_sync(0xffffffff, tm1, 1));
        tm1 = fmaxf(tm1, __shfl_xor_sync(0xffffffff, tm1, 2));

        const float mn0 = fmaxf(m0, tm0);
        const float mn1 = fmaxf(m1, tm1);
        const float cr0 = __expf(m0 - mn0);
        const float cr1 = __expf(m1 - mn1);
        m0 = mn0; m1 = mn1;

        float s0 = 0.f, s1 = 0.f;
#pragma unroll
        for (int nt = 0; nt < 8; nt++) {
            c_[nt][0] = __expf(c_[nt][0] - mn0);
            c_[nt][1] = __expf(c_[nt][1] - mn0);
            c_[nt][2] = __expf(c_[nt][2] - mn1);
            c_[nt][3] = __expf(c_[nt][3] - mn1);
            s0 += c_[nt][0] + c_[nt][1];
            s1 += c_[nt][2] + c_[nt][3];
        }
        l0 = l0 * cr0 + s0;
        l1 = l1 * cr1 + s1;
#pragma unroll
        for (int nt = 0; nt < 8; nt++) {
            acc[nt][0] *= cr0; acc[nt][1] *= cr0;
            acc[nt][2] *= cr1; acc[nt][3] *= cr1;
        }

        // ---- pack P C-frags into split A-frags (validated orderings) ----
        uint32_t ph[4][4], pl[4][4];
#pragma unroll
        for (int kt = 0; kt < 4; kt++) {
            split_pack(c_[2 * kt][0],     c_[2 * kt][1],     ph[kt][0], pl[kt][0]);
            split_pack(c_[2 * kt][2],     c_[2 * kt][3],     ph[kt][1], pl[kt][1]);
            split_pack(c_[2 * kt + 1][0], c_[2 * kt + 1][1], ph[kt][2], pl[kt][2]);
            split_pack(c_[2 * kt + 1][2], c_[2 * kt + 1][3], ph[kt][3], pl[kt][3]);
        }

        // ---- PV (V B-frags: GEMM-validated x2 on transposed VT tile) ----
#pragma unroll
        for (int kt = 0; kt < 4; kt++) {
            const int kb = kt * 16;
#pragma unroll
            for (int nt = 0; nt < 8; nt++) {
                uint32_t vh[2], vl[2];
                int row = nt * 8 + br;          // VT row = depth
                ldmatrix_x2(vh, smem_u32(&sVTh[row * LDVT + kb + bkq]));
                ldmatrix_x2(vl, smem_u32(&sVTl[row * LDVT + kb + bkq]));
                mma_bf16(acc[nt], ph[kt], vh);
                mma_bf16(acc[nt], ph[kt], vl);
                mma_bf16(acc[nt], pl[kt], vh);
            }
        }
    }

    // ---- finalize ----
    l0 += __shfl_xor_sync(0xffffffff, l0, 1);
    l0 += __shfl_xor_sync(0xffffffff, l0, 2);
    l1 += __shfl_xor_sync(0xffffffff, l1, 1);
    l1 += __shfl_xor_sync(0xffffffff, l1, 2);
    const float inv0 = 1.f / l0;
    const float inv1 = 1.f / l1;

#pragma unroll
    for (int nt = 0; nt < 8; nt++) {
        int col = nt * 8 + t * 2;
        size_t o0 = base + (size_t)r0g * D_MODEL + col;
        size_t o1 = base + (size_t)r1g * D_MODEL + col;
        *(float2*)(O + o0) = make_float2(acc[nt][0] * inv0, acc[nt][1] * inv0);
        *(float2*)(O + o1) = make_float2(acc[nt][2] * inv1, acc[nt][3] * inv1);
    }
}

// ---------------------------------------------------------------------------
// Launch: 0:v 1:k 2:q 3:mask 4:wq_w 5:wq_b 6:wk_w 7:wk_b 8:wv_w 9:wv_b
//         10:dense_w 11:dense_b
// ---------------------------------------------------------------------------
extern "C" void kernel_launch(void* const* d_in, const int* in_sizes, int n_in,
                              void* d_out, int out_size)
{
    const float* v       = (const float*)d_in[0];
    const float* k       = (const float*)d_in[1];
    const float* q       = (const float*)d_in[2];
    const float* wq_w    = (const float*)d_in[4];
    const float* wq_b    = (const float*)d_in[5];
    const float* wk_w    = (const float*)d_in[6];
    const float* wk_b    = (const float*)d_in[7];
    const float* wv_w    = (const float*)d_in[8];
    const float* wv_b    = (const float*)d_in[9];
    const float* dense_w = (const float*)d_in[10];
    const float* dense_b = (const float*)d_in[11];
    float* out = (float*)d_out;

    float *gq, *gk, *gv, *go;
    __nv_bfloat16 *ahi, *alo, *whi, *wlo, *qhi, *qlo, *khi, *klo, *vhi, *vlo;
    cudaGetSymbolAddress((void**)&gq, g_q);
    cudaGetSymbolAddress((void**)&gk, g_k);
    cudaGetSymbolAddress((void**)&gv, g_v);
    cudaGetSymbolAddress((void**)&go, g_o);
    cudaGetSymbolAddress((void**)&ahi, s_ahi);
    cudaGetSymbolAddress((void**)&alo, s_alo);
    cudaGetSymbolAddress((void**)&whi, s_whi);
    cudaGetSymbolAddress((void**)&wlo, s_wlo);
    cudaGetSymbolAddress((void**)&qhi, s_qhi);
    cudaGetSymbolAddress((void**)&qlo, s_qlo);
    cudaGetSymbolAddress((void**)&khi, s_khi);
    cudaGetSymbolAddress((void**)&klo, s_klo);
    cudaGetSymbolAddress((void**)&vhi, s_vhi);
    cudaGetSymbolAddress((void**)&vlo, s_vlo);

    cudaFuncSetAttribute(flash_mma, cudaFuncAttributeMaxDynamicSharedMemorySize, FLASH_SMEM);

    const int nact4 = NROWS * D_MODEL / 4;
    const int nw4   = D_MODEL * D_MODEL / 4;
    dim3 ggrid(GN / 64, NROWS / 128);   // (16, 32)

    split_bf16<<<nact4 / 256, 256>>>(q, ahi, alo, nact4);
    split_bf16<<<nw4 / 256, 256>>>(wq_w, whi, wlo, nw4);
    gemm_mma_split<<<ggrid, 256>>>(ahi, alo, whi, wlo, wq_b, gq);

    split_bf16<<<nact4 / 256, 256>>>(k, ahi, alo, nact4);
    split_bf16<<<nw4 / 256, 256>>>(wk_w, whi, wlo, nw4);
    gemm_mma_split<<<ggrid, 256>>>(ahi, alo, whi, wlo, wk_b, gk);

    split_bf16<<<nact4 / 256, 256>>>(v, ahi, alo, nact4);
    split_bf16<<<nw4 / 256, 256>>>(wv_w, whi, wlo, nw4);
    gemm_mma_split<<<ggrid, 256>>>(ahi, alo, whi, wlo, wv_b, gv);

    // split projected Q/K/V for tensor-core flash
    split_bf16<<<nact4 / 256, 256>>>(gq, qhi, qlo, nact4);
    split_bf16<<<nact4 / 256, 256>>>(gk, khi, klo, nact4);
    split_bf16<<<nact4 / 256, 256>>>(gv, vhi, vlo, nact4);

    dim3 fa_grid(SEQ / 128, BATCH * NHEADS);   // (16, 32)
    flash_mma<<<fa_grid, 256, FLASH_SMEM>>>(qhi, qlo, khi, klo, vhi, vlo, go);

    split_bf16<<<nact4 / 256, 256>>>(go, ahi, alo, nact4);
    split_bf16<<<nw4 / 256, 256>>>(dense_w, whi, wlo, nw4);
    gemm_mma_split<<<ggrid, 256>>>(ahi, alo, whi, wlo, dense_b, out);
}